// round 1
// baseline (speedup 1.0000x reference)
#include <cuda_runtime.h>
#include <math.h>

// Problem dims
#define S_   4096
#define T_   64
#define I_   64
#define EH_  128
#define E_   256
#define H_   512
#define O_   128
#define F1_  256
#define F2_  64
#define G4H_ (4*H_)       // 2048
#define ST_  (S_*T_)      // 262144

// ---------------- device scratch (no allocations allowed) ----------------
__device__ float g_laneC;
__device__ float g_x1[(size_t)ST_ * EH_];     // 128 MB
__device__ float g_xemb[(size_t)ST_ * E_];    // 256 MB
__device__ float g_gates[(size_t)S_ * G4H_];  // 32 MB
__device__ float g_h[(size_t)S_ * H_];
__device__ float g_hraw[(size_t)S_ * H_];
__device__ float g_c[(size_t)S_ * H_];
__device__ float g_o1[(size_t)S_ * O_];
__device__ float g_o2[(size_t)S_ * F1_];
__device__ float g_o3[(size_t)S_ * F2_];

__device__ __forceinline__ float sigm(float x) { return 1.0f / (1.0f + expf(-x)); }

// ---------------- lane gate (scalar) ----------------
__global__ void lane_kernel(const float* __restrict__ lane,
                            const float* __restrict__ Wlg1,
                            const float* __restrict__ blg1,
                            const float* __restrict__ Wlg2,
                            const float* __restrict__ blg2) {
    int j = threadIdx.x;  // 32 threads
    float lg = fmaxf(lane[0] * Wlg1[j] + blg1[j], 0.0f);
    float p = lg * Wlg2[j];
#pragma unroll
    for (int o = 16; o > 0; o >>= 1) p += __shfl_down_sync(0xFFFFFFFFu, p, o);
    if (j == 0) g_laneC = sigm(p + blg2[0]);
}

// ---------------- generic SGEMM: C = act(A @ B^T + bias) ----------------
// A: [M,K] row-major (lda), B: [N,K] row-major, C: [M,N] (ldc)
#define BM 128
#define BN 128
#define BK 8

__global__ __launch_bounds__(256)
void sgemm_nt(int M, int N, int K,
              const float* __restrict__ A, int lda,
              const float* __restrict__ B,
              const float* __restrict__ bias,
              float* __restrict__ C, int ldc,
              int doRelu, int scaleA)
{
    __shared__ __align__(16) float As[BK][BM];
    __shared__ __align__(16) float Bs[BK][BN];

    const int tid = threadIdx.x;
    const int tx = tid & 15;
    const int ty = tid >> 4;
    const int bm = blockIdx.y * BM;
    const int bn = blockIdx.x * BN;

    const float scale = scaleA ? g_laneC : 1.0f;

    const int lRow = tid >> 1;        // 0..127
    const int lCol = (tid & 1) * 4;   // 0 or 4

    float acc[8][8];
#pragma unroll
    for (int i = 0; i < 8; i++)
#pragma unroll
        for (int j = 0; j < 8; j++) acc[i][j] = 0.0f;

    for (int k0 = 0; k0 < K; k0 += BK) {
        float4 av = make_float4(0.f, 0.f, 0.f, 0.f);
        int ar = bm + lRow;
        if (ar < M) av = *reinterpret_cast<const float4*>(A + (size_t)ar * lda + (k0 + lCol));
        As[lCol + 0][lRow] = av.x * scale;
        As[lCol + 1][lRow] = av.y * scale;
        As[lCol + 2][lRow] = av.z * scale;
        As[lCol + 3][lRow] = av.w * scale;

        float4 bv = make_float4(0.f, 0.f, 0.f, 0.f);
        int br = bn + lRow;
        if (br < N) bv = *reinterpret_cast<const float4*>(B + (size_t)br * K + (k0 + lCol));
        Bs[lCol + 0][lRow] = bv.x;
        Bs[lCol + 1][lRow] = bv.y;
        Bs[lCol + 2][lRow] = bv.z;
        Bs[lCol + 3][lRow] = bv.w;

        __syncthreads();

#pragma unroll
        for (int k = 0; k < BK; k++) {
            float4 a0 = *reinterpret_cast<const float4*>(&As[k][ty * 4]);
            float4 a1 = *reinterpret_cast<const float4*>(&As[k][64 + ty * 4]);
            float4 b0 = *reinterpret_cast<const float4*>(&Bs[k][tx * 4]);
            float4 b1 = *reinterpret_cast<const float4*>(&Bs[k][64 + tx * 4]);
            float a[8] = {a0.x, a0.y, a0.z, a0.w, a1.x, a1.y, a1.z, a1.w};
            float b[8] = {b0.x, b0.y, b0.z, b0.w, b1.x, b1.y, b1.z, b1.w};
#pragma unroll
            for (int i = 0; i < 8; i++)
#pragma unroll
                for (int j = 0; j < 8; j++)
                    acc[i][j] = fmaf(a[i], b[j], acc[i][j]);
        }
        __syncthreads();
    }

#pragma unroll
    for (int i = 0; i < 8; i++) {
        int row = bm + ((i < 4) ? (ty * 4 + i) : (64 + ty * 4 + (i - 4)));
        if (row >= M) continue;
#pragma unroll
        for (int j = 0; j < 8; j++) {
            int col = bn + ((j < 4) ? (tx * 4 + j) : (64 + tx * 4 + (j - 4)));
            if (col >= N) continue;
            float v = acc[i][j];
            if (bias) v += bias[col];
            if (doRelu) v = fmaxf(v, 0.0f);
            C[(size_t)row * ldc + col] = v;
        }
    }
}

// ------------- per-step gates GEMM: gates = [x_t, h] @ [Wih;Whh]^T + bih + bhh -------------
// M=4096, N=2048, K=768 (first 256 from xemb at timestep t, rest from pooled h)
__global__ __launch_bounds__(256)
void gates_gemm(int t,
                const float* __restrict__ Wih,   // [2048,256]
                const float* __restrict__ Whh,   // [2048,512]
                const float* __restrict__ bih,
                const float* __restrict__ bhh)
{
    const int M = S_, N = G4H_, K = E_ + H_;  // 4096, 2048, 768
    __shared__ __align__(16) float As[BK][BM];
    __shared__ __align__(16) float Bs[BK][BN];

    const int tid = threadIdx.x;
    const int tx = tid & 15;
    const int ty = tid >> 4;
    const int bm = blockIdx.y * BM;
    const int bn = blockIdx.x * BN;

    const int lRow = tid >> 1;
    const int lCol = (tid & 1) * 4;

    float acc[8][8];
#pragma unroll
    for (int i = 0; i < 8; i++)
#pragma unroll
        for (int j = 0; j < 8; j++) acc[i][j] = 0.0f;

    for (int k0 = 0; k0 < K; k0 += BK) {
        int ar = bm + lRow;
        const float* aptr;
        if (k0 < E_) aptr = g_xemb + ((size_t)ar * T_ + t) * E_ + (k0 + lCol);
        else         aptr = g_h    + (size_t)ar * H_ + (k0 - E_ + lCol);
        float4 av = *reinterpret_cast<const float4*>(aptr);
        As[lCol + 0][lRow] = av.x;
        As[lCol + 1][lRow] = av.y;
        As[lCol + 2][lRow] = av.z;
        As[lCol + 3][lRow] = av.w;

        int br = bn + lRow;
        const float* bptr;
        if (k0 < E_) bptr = Wih + (size_t)br * E_ + (k0 + lCol);
        else         bptr = Whh + (size_t)br * H_ + (k0 - E_ + lCol);
        float4 bv = *reinterpret_cast<const float4*>(bptr);
        Bs[lCol + 0][lRow] = bv.x;
        Bs[lCol + 1][lRow] = bv.y;
        Bs[lCol + 2][lRow] = bv.z;
        Bs[lCol + 3][lRow] = bv.w;

        __syncthreads();

#pragma unroll
        for (int k = 0; k < BK; k++) {
            float4 a0 = *reinterpret_cast<const float4*>(&As[k][ty * 4]);
            float4 a1 = *reinterpret_cast<const float4*>(&As[k][64 + ty * 4]);
            float4 b0 = *reinterpret_cast<const float4*>(&Bs[k][tx * 4]);
            float4 b1 = *reinterpret_cast<const float4*>(&Bs[k][64 + tx * 4]);
            float a[8] = {a0.x, a0.y, a0.z, a0.w, a1.x, a1.y, a1.z, a1.w};
            float b[8] = {b0.x, b0.y, b0.z, b0.w, b1.x, b1.y, b1.z, b1.w};
#pragma unroll
            for (int i = 0; i < 8; i++)
#pragma unroll
                for (int j = 0; j < 8; j++)
                    acc[i][j] = fmaf(a[i], b[j], acc[i][j]);
        }
        __syncthreads();
    }

#pragma unroll
    for (int i = 0; i < 8; i++) {
        int row = bm + ((i < 4) ? (ty * 4 + i) : (64 + ty * 4 + (i - 4)));
#pragma unroll
        for (int j = 0; j < 8; j++) {
            int col = bn + ((j < 4) ? (tx * 4 + j) : (64 + tx * 4 + (j - 4)));
            g_gates[(size_t)row * G4H_ + col] = acc[i][j] + bih[col] + bhh[col];
        }
    }
}

// ---------------- LSTM elementwise cell ----------------
__global__ void lstm_cell_kernel() {
    int idx = blockIdx.x * blockDim.x + threadIdx.x;
    if (idx >= S_ * H_) return;
    int s = idx >> 9;        // /512
    int j = idx & (H_ - 1);
    const float* g = g_gates + (size_t)s * G4H_;
    float ig = sigm(g[j]);
    float fg = sigm(g[H_ + j]);
    float gg = tanhf(g[2 * H_ + j]);
    float og = sigm(g[3 * H_ + j]);
    float cn = fg * g_c[idx] + ig * gg;
    g_c[idx] = cn;
    g_hraw[idx] = og * tanhf(cn);
}

// ---------------- spatial maxpool (kernel 3, stride 1, pad 1, -inf pad) ----------------
__global__ void maxpool_kernel() {
    int idx = blockIdx.x * blockDim.x + threadIdx.x;
    if (idx >= S_ * H_) return;
    int s = idx >> 9;
    float v = g_hraw[idx];
    if (s > 0)       v = fmaxf(v, g_hraw[idx - H_]);
    if (s < S_ - 1)  v = fmaxf(v, g_hraw[idx + H_]);
    g_h[idx] = v;
}

// ---------------- init h,c = 0 ----------------
__global__ void zero_hc_kernel() {
    int idx = blockIdx.x * blockDim.x + threadIdx.x;
    if (idx >= S_ * H_) return;
    g_h[idx] = 0.0f;
    g_c[idx] = 0.0f;
}

// ---------------- final head: out[s] = (o3[s,:] . Wf3 + bf3) / laneC ----------------
__global__ void head_final_kernel(const float* __restrict__ Wf3,
                                  const float* __restrict__ bf3,
                                  float* __restrict__ out) {
    __shared__ float red[F2_];
    int s = blockIdx.x;
    int t = threadIdx.x;  // 64
    red[t] = g_o3[(size_t)s * F2_ + t] * Wf3[t];
    __syncthreads();
#pragma unroll
    for (int o = 32; o > 0; o >>= 1) {
        if (t < o) red[t] += red[t + o];
        __syncthreads();
    }
    if (t == 0) out[s] = (red[0] + bf3[0]) / g_laneC;
}

// ---------------- copy h, c into d_out ----------------
__global__ void finalize_kernel(float* __restrict__ out) {
    int idx = blockIdx.x * blockDim.x + threadIdx.x;
    if (idx >= S_ * H_) return;
    out[S_ + idx] = g_h[idx];
    out[S_ + (size_t)S_ * H_ + idx] = g_c[idx];
}

// ---------------- host launcher ----------------
extern "C" void kernel_launch(void* const* d_in, const int* in_sizes, int n_in,
                              void* d_out, int out_size) {
    const float* inputData = (const float*)d_in[0];
    const float* lane      = (const float*)d_in[1];
    const float* Wlg1      = (const float*)d_in[2];
    const float* blg1      = (const float*)d_in[3];
    const float* Wlg2      = (const float*)d_in[4];
    const float* blg2      = (const float*)d_in[5];
    const float* We1       = (const float*)d_in[6];
    const float* be1       = (const float*)d_in[7];
    const float* We2       = (const float*)d_in[8];
    const float* be2       = (const float*)d_in[9];
    const float* Wih       = (const float*)d_in[10];
    const float* bih       = (const float*)d_in[11];
    const float* Whh       = (const float*)d_in[12];
    const float* bhh       = (const float*)d_in[13];
    const float* Wout      = (const float*)d_in[14];
    const float* bout      = (const float*)d_in[15];
    const float* Wf1       = (const float*)d_in[16];
    const float* bf1       = (const float*)d_in[17];
    const float* Wf2       = (const float*)d_in[18];
    const float* bf2       = (const float*)d_in[19];
    const float* Wf3       = (const float*)d_in[20];
    const float* bf3       = (const float*)d_in[21];
    float* out = (float*)d_out;

    float *p_x1, *p_xemb, *p_h, *p_o1, *p_o2, *p_o3;
    cudaGetSymbolAddress((void**)&p_x1,   g_x1);
    cudaGetSymbolAddress((void**)&p_xemb, g_xemb);
    cudaGetSymbolAddress((void**)&p_h,    g_h);
    cudaGetSymbolAddress((void**)&p_o1,   g_o1);
    cudaGetSymbolAddress((void**)&p_o2,   g_o2);
    cudaGetSymbolAddress((void**)&p_o3,   g_o3);

    // 1) lane gate scalar
    lane_kernel<<<1, 32>>>(lane, Wlg1, blg1, Wlg2, blg2);

    dim3 blk(256);

    // 2) embedding MLP (laneC scaling folded into A-loads of GEMM1)
    sgemm_nt<<<dim3(EH_ / BN, ST_ / BM), blk>>>(ST_, EH_, I_, inputData, I_, We1, be1,
                                                p_x1, EH_, 1, 1);
    sgemm_nt<<<dim3(E_ / BN, ST_ / BM), blk>>>(ST_, E_, EH_, p_x1, EH_, We2, be2,
                                               p_xemb, E_, 1, 0);

    // 3) init h, c
    int ew = S_ * H_;  // 2097152
    zero_hc_kernel<<<(ew + 255) / 256, 256>>>();

    // 4) recurrence
    dim3 ggrid(G4H_ / BN, S_ / BM);  // 16 x 32
    for (int t = 0; t < T_; t++) {
        gates_gemm<<<ggrid, blk>>>(t, Wih, Whh, bih, bhh);
        lstm_cell_kernel<<<(ew + 255) / 256, 256>>>();
        maxpool_kernel<<<(ew + 255) / 256, 256>>>();
    }

    // 5) output head
    sgemm_nt<<<dim3(O_ / BN, S_ / BM), blk>>>(S_, O_, H_, p_h, H_, Wout, bout,
                                              p_o1, O_, 0, 0);
    sgemm_nt<<<dim3((F1_ + BN - 1) / BN, S_ / BM), blk>>>(S_, F1_, O_, p_o1, O_, Wf1, bf1,
                                                          p_o2, F1_, 1, 0);
    sgemm_nt<<<dim3((F2_ + BN - 1) / BN, S_ / BM), blk>>>(S_, F2_, F1_, p_o2, F1_, Wf2, bf2,
                                                          p_o3, F2_, 1, 0);
    head_final_kernel<<<S_, F2_>>>(Wf3, bf3, out);

    // 6) emit h and c
    finalize_kernel<<<(ew + 255) / 256, 256>>>(out);
}

// round 2
// speedup vs baseline: 1.1168x; 1.1168x over previous
#include <cuda_runtime.h>
#include <math.h>

typedef unsigned long long ull;

// Problem dims
#define S_   4096
#define T_   64
#define I_   64
#define EH_  128
#define E_   256
#define H_   512
#define O_   128
#define F1_  256
#define F2_  64
#define G4H_ (4*H_)       // 2048
#define KG_  (E_+H_)      // 768
#define ST_  (S_*T_)      // 262144

// ---------------- device scratch ----------------
__device__ float g_laneC;
__device__ float g_x1[(size_t)ST_ * EH_];     // 128 MB
__device__ float g_xemb[(size_t)ST_ * E_];    // 256 MB, layout [T][S][E]
__device__ float g_Wcomb[(size_t)G4H_ * KG_]; // interleaved [j*4+gate][768]
__device__ float g_bcomb[G4H_];
__device__ float g_h[(size_t)S_ * H_];
__device__ float g_hraw[(size_t)S_ * H_];
__device__ float g_c[(size_t)S_ * H_];
__device__ float g_o1[(size_t)S_ * O_];
__device__ float g_o2[(size_t)S_ * F1_];
__device__ float g_o3[(size_t)S_ * F2_];

// packed f32x2 helpers (sm_103a FFMA2 — PTX-only path)
#define FMA2(d, a, b) asm("fma.rn.f32x2 %0, %1, %2, %0;" : "+l"(d) : "l"(a), "l"(b))
#define PACK2(d, x)   asm("mov.b64 %0, {%1, %1};" : "=l"(d) : "f"(x))

__device__ __forceinline__ float2 unpk(ull v) {
    float2 r;
    asm("mov.b64 {%0, %1}, %2;" : "=f"(r.x), "=f"(r.y) : "l"(v));
    return r;
}

__device__ __forceinline__ float sigf(float x) {
    return __fdividef(1.0f, 1.0f + __expf(-x));
}
__device__ __forceinline__ float tanhf_(float x) {
    // 2*sigmoid(2x)-1 : saturates cleanly for |x| large
    return 2.0f * __fdividef(1.0f, 1.0f + __expf(-2.0f * x)) - 1.0f;
}

// ---------------- lane gate (scalar) ----------------
__global__ void lane_kernel(const float* __restrict__ lane,
                            const float* __restrict__ Wlg1,
                            const float* __restrict__ blg1,
                            const float* __restrict__ Wlg2,
                            const float* __restrict__ blg2) {
    int j = threadIdx.x;  // 32
    float lg = fmaxf(lane[0] * Wlg1[j] + blg1[j], 0.0f);
    float p = lg * Wlg2[j];
#pragma unroll
    for (int o = 16; o > 0; o >>= 1) p += __shfl_down_sync(0xFFFFFFFFu, p, o);
    if (j == 0) g_laneC = 1.0f / (1.0f + expf(-(p + blg2[0])));
}

// ---------------- weight interleave prep: row r=j*4+gate <- gate*512+j ----------------
__global__ void prep_weights(const float* __restrict__ Wih,  // [2048,256]
                             const float* __restrict__ Whh,  // [2048,512]
                             const float* __restrict__ bih,
                             const float* __restrict__ bhh) {
    int r = blockIdx.x;                 // 0..2047 interleaved row
    int orig = (r & 3) * H_ + (r >> 2); // original torch row
    float* dst = g_Wcomb + (size_t)r * KG_;
    for (int k = threadIdx.x; k < KG_; k += blockDim.x)
        dst[k] = (k < E_) ? Wih[(size_t)orig * E_ + k]
                          : Whh[(size_t)orig * H_ + (k - E_)];
    if (threadIdx.x == 0) g_bcomb[r] = bih[orig] + bhh[orig];
}

// ---------------- generic FFMA2 SGEMM: C = act(A @ B^T + bias) ----------------
#define BM 128
#define BN 128
#define BK 8
#define FL_RELU    1
#define FL_SCALEA  2
#define FL_PERMT   4

__global__ __launch_bounds__(256, 2)
void sgemm2(int M, int N, int K,
            const float* __restrict__ A, int lda,
            const float* __restrict__ B,
            const float* __restrict__ bias,
            float* __restrict__ C, int ldc, int flags)
{
    __shared__ __align__(16) float As[BK][BM];
    __shared__ __align__(16) float Bs[BK][BN];

    const int tid = threadIdx.x;
    const int tx = tid & 15;
    const int ty = tid >> 4;
    const int bm = blockIdx.y * BM;
    const int bn = blockIdx.x * BN;
    const float scale = (flags & FL_SCALEA) ? g_laneC : 1.0f;
    const int lRow = tid >> 1;
    const int lCol = (tid & 1) * 4;

    ull acc[8][4];
#pragma unroll
    for (int i = 0; i < 8; i++)
#pragma unroll
        for (int p = 0; p < 4; p++) acc[i][p] = 0ull;

    for (int k0 = 0; k0 < K; k0 += BK) {
        float4 av = make_float4(0.f, 0.f, 0.f, 0.f);
        int ar = bm + lRow;
        if (ar < M) av = *reinterpret_cast<const float4*>(A + (size_t)ar * lda + (k0 + lCol));
        As[lCol + 0][lRow] = av.x * scale;
        As[lCol + 1][lRow] = av.y * scale;
        As[lCol + 2][lRow] = av.z * scale;
        As[lCol + 3][lRow] = av.w * scale;

        float4 bv = make_float4(0.f, 0.f, 0.f, 0.f);
        int br = bn + lRow;
        if (br < N) bv = *reinterpret_cast<const float4*>(B + (size_t)br * K + (k0 + lCol));
        Bs[lCol + 0][lRow] = bv.x;
        Bs[lCol + 1][lRow] = bv.y;
        Bs[lCol + 2][lRow] = bv.z;
        Bs[lCol + 3][lRow] = bv.w;

        __syncthreads();

#pragma unroll
        for (int k = 0; k < BK; k++) {
            float4 a0 = *reinterpret_cast<const float4*>(&As[k][ty * 4]);
            float4 a1 = *reinterpret_cast<const float4*>(&As[k][64 + ty * 4]);
            const ull* bp0 = reinterpret_cast<const ull*>(&Bs[k][tx * 4]);
            const ull* bp1 = reinterpret_cast<const ull*>(&Bs[k][64 + tx * 4]);
            ull b0 = bp0[0], b1 = bp0[1], b2 = bp1[0], b3 = bp1[1];
            float as[8] = {a0.x, a0.y, a0.z, a0.w, a1.x, a1.y, a1.z, a1.w};
            ull aa;
#pragma unroll
            for (int i = 0; i < 8; i++) {
                PACK2(aa, as[i]);
                FMA2(acc[i][0], aa, b0);
                FMA2(acc[i][1], aa, b1);
                FMA2(acc[i][2], aa, b2);
                FMA2(acc[i][3], aa, b3);
            }
        }
        __syncthreads();
    }

#pragma unroll
    for (int i = 0; i < 8; i++) {
        int row = bm + ((i < 4) ? (ty * 4 + i) : (64 + ty * 4 + (i - 4)));
        if (row >= M) continue;
        size_t orow = (flags & FL_PERMT)
                      ? ((size_t)(row % T_) * S_ + (row / T_))
                      : (size_t)row;
#pragma unroll
        for (int p = 0; p < 4; p++) {
            float2 v = unpk(acc[i][p]);
            int c0 = bn + ((p < 2) ? (tx * 4 + p * 2) : (64 + tx * 4 + (p - 2) * 2));
#pragma unroll
            for (int q = 0; q < 2; q++) {
                int col = c0 + q;
                if (col >= N) continue;
                float val = (q == 0) ? v.x : v.y;
                if (bias) val += bias[col];
                if (flags & FL_RELU) val = fmaxf(val, 0.0f);
                C[orow * ldc + col] = val;
            }
        }
    }
}

// ------------- per-step gates GEMM + fused LSTM cell -------------
// gates = [xemb_t, h] @ Wcomb^T + bcomb (interleaved cols: j*4 + {i,f,g,o})
// epilogue computes c,hraw directly.
__global__ __launch_bounds__(256, 2)
void gates_cell_gemm(int t)
{
    __shared__ __align__(16) float As[BK][BM];
    __shared__ __align__(16) float Bs[BK][BN];

    const int tid = threadIdx.x;
    const int tx = tid & 15;
    const int ty = tid >> 4;
    const int bm = blockIdx.y * BM;
    const int bn = blockIdx.x * BN;
    const int lRow = tid >> 1;
    const int lCol = (tid & 1) * 4;

    ull acc[8][4];
#pragma unroll
    for (int i = 0; i < 8; i++)
#pragma unroll
        for (int p = 0; p < 4; p++) acc[i][p] = 0ull;

    const float* xslice = g_xemb + (size_t)t * S_ * E_;

    for (int k0 = 0; k0 < KG_; k0 += BK) {
        int ar = bm + lRow;
        const float* aptr = (k0 < E_)
            ? xslice + (size_t)ar * E_ + (k0 + lCol)
            : g_h + (size_t)ar * H_ + (k0 - E_ + lCol);
        float4 av = *reinterpret_cast<const float4*>(aptr);
        As[lCol + 0][lRow] = av.x;
        As[lCol + 1][lRow] = av.y;
        As[lCol + 2][lRow] = av.z;
        As[lCol + 3][lRow] = av.w;

        int br = bn + lRow;
        float4 bv = *reinterpret_cast<const float4*>(g_Wcomb + (size_t)br * KG_ + (k0 + lCol));
        Bs[lCol + 0][lRow] = bv.x;
        Bs[lCol + 1][lRow] = bv.y;
        Bs[lCol + 2][lRow] = bv.z;
        Bs[lCol + 3][lRow] = bv.w;

        __syncthreads();

#pragma unroll
        for (int k = 0; k < BK; k++) {
            float4 a0 = *reinterpret_cast<const float4*>(&As[k][ty * 4]);
            float4 a1 = *reinterpret_cast<const float4*>(&As[k][64 + ty * 4]);
            const ull* bp0 = reinterpret_cast<const ull*>(&Bs[k][tx * 4]);
            const ull* bp1 = reinterpret_cast<const ull*>(&Bs[k][64 + tx * 4]);
            ull b0 = bp0[0], b1 = bp0[1], b2 = bp1[0], b3 = bp1[1];
            float as[8] = {a0.x, a0.y, a0.z, a0.w, a1.x, a1.y, a1.z, a1.w};
            ull aa;
#pragma unroll
            for (int i = 0; i < 8; i++) {
                PACK2(aa, as[i]);
                FMA2(acc[i][0], aa, b0);
                FMA2(acc[i][1], aa, b1);
                FMA2(acc[i][2], aa, b2);
                FMA2(acc[i][3], aa, b3);
            }
        }
        __syncthreads();
    }

    // bias for this thread's 8 cols (two gate-units)
    float4 bA = *reinterpret_cast<const float4*>(&g_bcomb[bn + tx * 4]);
    float4 bB = *reinterpret_cast<const float4*>(&g_bcomb[bn + 64 + tx * 4]);
    int unitA = (bn >> 2) + tx;        // h-index for group A
    int unitB = (bn >> 2) + 16 + tx;   // h-index for group B

#pragma unroll
    for (int i = 0; i < 8; i++) {
        int s = bm + ((i < 4) ? (ty * 4 + i) : (64 + ty * 4 + (i - 4)));
        // group A: pairs 0 (i,f), 1 (g,o)
        {
            float2 p0 = unpk(acc[i][0]);
            float2 p1 = unpk(acc[i][1]);
            float ig = sigf(p0.x + bA.x);
            float fg = sigf(p0.y + bA.y);
            float gg = tanhf_(p1.x + bA.z);
            float og = sigf(p1.y + bA.w);
            size_t idx = (size_t)s * H_ + unitA;
            float cn = fg * g_c[idx] + ig * gg;
            g_c[idx] = cn;
            g_hraw[idx] = og * tanhf_(cn);
        }
        // group B: pairs 2 (i,f), 3 (g,o)
        {
            float2 p0 = unpk(acc[i][2]);
            float2 p1 = unpk(acc[i][3]);
            float ig = sigf(p0.x + bB.x);
            float fg = sigf(p0.y + bB.y);
            float gg = tanhf_(p1.x + bB.z);
            float og = sigf(p1.y + bB.w);
            size_t idx = (size_t)s * H_ + unitB;
            float cn = fg * g_c[idx] + ig * gg;
            g_c[idx] = cn;
            g_hraw[idx] = og * tanhf_(cn);
        }
    }
}

// ---------------- spatial maxpool (k=3, s=1, p=1, -inf pad) ----------------
__global__ void maxpool_kernel() {
    int idx = blockIdx.x * blockDim.x + threadIdx.x;
    if (idx >= S_ * H_) return;
    int s = idx >> 9;
    float v = g_hraw[idx];
    if (s > 0)       v = fmaxf(v, g_hraw[idx - H_]);
    if (s < S_ - 1)  v = fmaxf(v, g_hraw[idx + H_]);
    g_h[idx] = v;
}

__global__ void zero_hc_kernel() {
    int idx = blockIdx.x * blockDim.x + threadIdx.x;
    if (idx >= S_ * H_) return;
    g_h[idx] = 0.0f;
    g_c[idx] = 0.0f;
}

// ---------------- final head: out[s] = (o3[s,:] . Wf3 + bf3) / laneC ----------------
__global__ void head_final_kernel(const float* __restrict__ Wf3,
                                  const float* __restrict__ bf3,
                                  float* __restrict__ out) {
    __shared__ float red[F2_];
    int s = blockIdx.x;
    int t = threadIdx.x;  // 64
    red[t] = g_o3[(size_t)s * F2_ + t] * Wf3[t];
    __syncthreads();
#pragma unroll
    for (int o = 32; o > 0; o >>= 1) {
        if (t < o) red[t] += red[t + o];
        __syncthreads();
    }
    if (t == 0) out[s] = (red[0] + bf3[0]) / g_laneC;
}

// ---------------- copy h, c into d_out ----------------
__global__ void finalize_kernel(float* __restrict__ out) {
    int idx = blockIdx.x * blockDim.x + threadIdx.x;
    if (idx >= S_ * H_) return;
    out[S_ + idx] = g_h[idx];
    out[S_ + (size_t)S_ * H_ + idx] = g_c[idx];
}

// ---------------- host launcher ----------------
extern "C" void kernel_launch(void* const* d_in, const int* in_sizes, int n_in,
                              void* d_out, int out_size) {
    const float* inputData = (const float*)d_in[0];
    const float* lane      = (const float*)d_in[1];
    const float* Wlg1      = (const float*)d_in[2];
    const float* blg1      = (const float*)d_in[3];
    const float* Wlg2      = (const float*)d_in[4];
    const float* blg2      = (const float*)d_in[5];
    const float* We1       = (const float*)d_in[6];
    const float* be1       = (const float*)d_in[7];
    const float* We2       = (const float*)d_in[8];
    const float* be2       = (const float*)d_in[9];
    const float* Wih       = (const float*)d_in[10];
    const float* bih       = (const float*)d_in[11];
    const float* Whh       = (const float*)d_in[12];
    const float* bhh       = (const float*)d_in[13];
    const float* Wout      = (const float*)d_in[14];
    const float* bout      = (const float*)d_in[15];
    const float* Wf1       = (const float*)d_in[16];
    const float* bf1       = (const float*)d_in[17];
    const float* Wf2       = (const float*)d_in[18];
    const float* bf2       = (const float*)d_in[19];
    const float* Wf3       = (const float*)d_in[20];
    const float* bf3       = (const float*)d_in[21];
    float* out = (float*)d_out;

    float *p_x1, *p_xemb, *p_h, *p_o1, *p_o2, *p_o3;
    cudaGetSymbolAddress((void**)&p_x1,   g_x1);
    cudaGetSymbolAddress((void**)&p_xemb, g_xemb);
    cudaGetSymbolAddress((void**)&p_h,    g_h);
    cudaGetSymbolAddress((void**)&p_o1,   g_o1);
    cudaGetSymbolAddress((void**)&p_o2,   g_o2);
    cudaGetSymbolAddress((void**)&p_o3,   g_o3);

    dim3 blk(256);

    // weight interleave + lane gate
    prep_weights<<<G4H_, 256>>>(Wih, Whh, bih, bhh);
    lane_kernel<<<1, 32>>>(lane, Wlg1, blg1, Wlg2, blg2);

    // embedding MLP; second GEMM permutes output to [T][S][E]
    sgemm2<<<dim3(EH_ / BN, ST_ / BM), blk>>>(ST_, EH_, I_, inputData, I_, We1, be1,
                                              p_x1, EH_, FL_RELU | FL_SCALEA);
    sgemm2<<<dim3(E_ / BN, ST_ / BM), blk>>>(ST_, E_, EH_, p_x1, EH_, We2, be2,
                                             p_xemb, E_, FL_RELU | FL_PERMT);

    int ew = S_ * H_;
    zero_hc_kernel<<<(ew + 255) / 256, 256>>>();

    // recurrence: fused GEMM+cell, then maxpool
    dim3 ggrid(G4H_ / BN, S_ / BM);  // 16 x 32
    for (int t = 0; t < T_; t++) {
        gates_cell_gemm<<<ggrid, blk>>>(t);
        maxpool_kernel<<<(ew + 255) / 256, 256>>>();
    }

    // output head
    sgemm2<<<dim3(O_ / BN, S_ / BM), blk>>>(S_, O_, H_, p_h, H_, Wout, bout,
                                            p_o1, O_, 0);
    sgemm2<<<dim3((F1_ + BN - 1) / BN, S_ / BM), blk>>>(S_, F1_, O_, p_o1, O_, Wf1, bf1,
                                                        p_o2, F1_, FL_RELU);
    sgemm2<<<dim3((F2_ + BN - 1) / BN, S_ / BM), blk>>>(S_, F2_, F1_, p_o2, F1_, Wf2, bf2,
                                                        p_o3, F2_, FL_RELU);
    head_final_kernel<<<S_, F2_>>>(Wf3, bf3, out);
    finalize_kernel<<<(ew + 255) / 256, 256>>>(out);
}